// round 1
// baseline (speedup 1.0000x reference)
#include <cuda_runtime.h>
#include <cuda_bf16.h>
#include <math.h>

// Problem constants (from reference: Bsz=4, S=2048, Din=Dout=768, GRID_NUM=3, K=3)
#define DIN   768
#define DOUT  768
#define NMAX  8192
#define JPER  7              // 1 silu + 6 basis values per input feature
#define KDIM  (DIN * JPER)   // 5376

// Scratch (allocation-free rule: __device__ globals)
__device__ float g_A[(size_t)NMAX * KDIM];   // N x K   (176 MB)
__device__ float g_W[(size_t)KDIM * DOUT];   // K x Dout (16.5 MB)

// ---------------------------------------------------------------------------
// Kernel 1: fold weights  Wt[k][o],  k = i*7 + j
// ---------------------------------------------------------------------------
__global__ void build_W(const float* __restrict__ coef,
                        const float* __restrict__ scale_base,
                        const float* __restrict__ scale_sp) {
    int idx = blockIdx.x * blockDim.x + threadIdx.x;
    if (idx >= DIN * DOUT) return;
    int o = idx % DOUT;          // fastest -> coalesced writes to g_W
    int i = idx / DOUT;
    g_W[(size_t)(i * JPER + 0) * DOUT + o] = scale_base[(size_t)o * DIN + i];
    float s = scale_sp[(size_t)o * DIN + i];
    const float* c = coef + ((size_t)o * DIN + i) * 6;
#pragma unroll
    for (int m = 0; m < 6; m++)
        g_W[(size_t)(i * JPER + 1 + m) * DOUT + o] = s * c[m];
}

// ---------------------------------------------------------------------------
// Kernel 2: augmented activations A[n][i*7 + j]
//   j=0: silu(x); j=1..6: cubic B-spline basis (Cox-de Boor, uniform grid)
// ---------------------------------------------------------------------------
__global__ void build_A(const float* __restrict__ x, int total) {
    int idx = blockIdx.x * blockDim.x + threadIdx.x;
    if (idx >= total) return;
    float v = x[idx];
    int n = idx / DIN;
    int i = idx % DIN;
    float* dst = g_A + (size_t)n * KDIM + i * JPER;

    float out[JPER];
    // silu
    out[0] = v / (1.0f + expf(-v));

    // extended grid: g[t] = (t-3)*(2/3) - 1, t=0..9
    const float h = 2.0f / 3.0f;
    float g[10];
#pragma unroll
    for (int t = 0; t < 10; t++) g[t] = (float)(t - 3) * h - 1.0f;

    float B0[9];
#pragma unroll
    for (int t = 0; t < 9; t++)
        B0[t] = (v >= g[t] && v < g[t + 1]) ? 1.0f : 0.0f;
    float B1[8];
#pragma unroll
    for (int t = 0; t < 8; t++)
        B1[t] = (v - g[t]) / (g[t + 1] - g[t]) * B0[t]
              + (g[t + 2] - v) / (g[t + 2] - g[t + 1]) * B0[t + 1];
    float B2[7];
#pragma unroll
    for (int t = 0; t < 7; t++)
        B2[t] = (v - g[t]) / (g[t + 2] - g[t]) * B1[t]
              + (g[t + 3] - v) / (g[t + 3] - g[t + 1]) * B1[t + 1];
    float B3[6];
#pragma unroll
    for (int t = 0; t < 6; t++)
        B3[t] = (v - g[t]) / (g[t + 3] - g[t]) * B2[t]
              + (g[t + 4] - v) / (g[t + 4] - g[t + 1]) * B2[t + 1];
#pragma unroll
    for (int m = 0; m < 6; m++) out[1 + m] = B3[m];

#pragma unroll
    for (int j = 0; j < JPER; j++) dst[j] = out[j];
}

// ---------------------------------------------------------------------------
// Kernel 3: SGEMM  C[N x 768] = A[N x 5376] * Wt[5376 x 768] + bias
//   128x128 block tile, BK=16, 256 threads, 8x8 microtile
// ---------------------------------------------------------------------------
#define BM 128
#define BN 128
#define BK 16

__global__ __launch_bounds__(256, 2) void sgemm_kan(const float* __restrict__ bias,
                                                    float* __restrict__ C) {
    __shared__ float As[BK][BM];   // transposed A tile
    __shared__ float Bs[BK][BN];

    const int bx = blockIdx.x;     // over DOUT/128 = 6
    const int by = blockIdx.y;     // over N/128
    const int tid = threadIdx.x;
    const int tx = tid % 16;
    const int ty = tid / 16;

    const float* Ablk = g_A + (size_t)by * BM * KDIM;
    const float* Bblk = g_W + bx * BN;

    float acc[8][8];
#pragma unroll
    for (int i = 0; i < 8; i++)
#pragma unroll
        for (int j = 0; j < 8; j++) acc[i][j] = 0.0f;

    const int aRow = tid / 4;              // 0..63, +64
    const int aCol = (tid % 4) * 4;        // 0,4,8,12
    const int bRow = tid / 32;             // 0..7, +8
    const int bCol = (tid % 32) * 4;       // 0..124

    for (int k0 = 0; k0 < KDIM; k0 += BK) {
        // load A tile (transposed into smem)
#pragma unroll
        for (int r = 0; r < 2; r++) {
            int row = aRow + r * 64;
            float4 v = *(const float4*)(Ablk + (size_t)row * KDIM + k0 + aCol);
            As[aCol + 0][row] = v.x;
            As[aCol + 1][row] = v.y;
            As[aCol + 2][row] = v.z;
            As[aCol + 3][row] = v.w;
        }
        // load B tile
#pragma unroll
        for (int r = 0; r < 2; r++) {
            int row = bRow + r * 8;
            float4 v = *(const float4*)(Bblk + (size_t)(k0 + row) * DOUT + bCol);
            *(float4*)&Bs[row][bCol] = v;
        }
        __syncthreads();

#pragma unroll
        for (int k = 0; k < BK; k++) {
            float a[8], b[8];
            *(float4*)(a)     = *(const float4*)&As[k][ty * 4];
            *(float4*)(a + 4) = *(const float4*)&As[k][ty * 4 + 64];
            *(float4*)(b)     = *(const float4*)&Bs[k][tx * 4];
            *(float4*)(b + 4) = *(const float4*)&Bs[k][tx * 4 + 64];
#pragma unroll
            for (int i = 0; i < 8; i++)
#pragma unroll
                for (int j = 0; j < 8; j++) acc[i][j] = fmaf(a[i], b[j], acc[i][j]);
        }
        __syncthreads();
    }

    // epilogue: add bias, write out
#pragma unroll
    for (int ii = 0; ii < 2; ii++) {
#pragma unroll
        for (int i = 0; i < 4; i++) {
            int row = by * BM + ii * 64 + ty * 4 + i;
#pragma unroll
            for (int jj = 0; jj < 2; jj++) {
                int col = bx * BN + jj * 64 + tx * 4;
                float4 v;
                v.x = acc[ii * 4 + i][jj * 4 + 0] + bias[col + 0];
                v.y = acc[ii * 4 + i][jj * 4 + 1] + bias[col + 1];
                v.z = acc[ii * 4 + i][jj * 4 + 2] + bias[col + 2];
                v.w = acc[ii * 4 + i][jj * 4 + 3] + bias[col + 3];
                *(float4*)&C[(size_t)row * DOUT + col] = v;
            }
        }
    }
}

// ---------------------------------------------------------------------------
extern "C" void kernel_launch(void* const* d_in, const int* in_sizes, int n_in,
                              void* d_out, int out_size) {
    const float* x          = (const float*)d_in[0];   // (4,2048,768)
    const float* coef       = (const float*)d_in[1];   // (768,768,6)
    const float* scale_base = (const float*)d_in[2];   // (768,768)
    const float* scale_sp   = (const float*)d_in[3];   // (768,768)
    const float* bias       = (const float*)d_in[4];   // (768,)
    float* out = (float*)d_out;

    int N = in_sizes[0] / DIN;     // 8192
    int totalX = N * DIN;

    build_W<<<(DIN * DOUT + 255) / 256, 256>>>(coef, scale_base, scale_sp);
    build_A<<<(totalX + 255) / 256, 256>>>(x, totalX);

    dim3 grid(DOUT / BN, N / BM);  // (6, 64)
    sgemm_kan<<<grid, 256>>>(bias, out);
}

// round 4
// speedup vs baseline: 2.0191x; 2.0191x over previous
#include <cuda_runtime.h>
#include <cuda_bf16.h>
#include <math.h>
#include <cstdint>

#define DIN   768
#define DOUT  768
#define NMAX  8192
#define JPER  7
#define KDIM  (DIN * JPER)   // 5376

// GEMM tiling
#define MT    128
#define NT    128
#define BK    32                 // K per chunk (bf16 elems)
#define NCHUNK (KDIM / BK)       // 168
#define PAD_ROW 40               // 32 + 8 bf16 padding -> 80B row stride
#define ROWB  (PAD_ROW * 2)      // 80 bytes

// Scratch: split-bf16 activations and folded weights (K-major both)
__device__ __align__(128) __nv_bfloat16 g_Ahi[(size_t)NMAX * KDIM];
__device__ __align__(128) __nv_bfloat16 g_Alo[(size_t)NMAX * KDIM];
__device__ __align__(128) __nv_bfloat16 g_Whi[(size_t)DOUT * KDIM];
__device__ __align__(128) __nv_bfloat16 g_Wlo[(size_t)DOUT * KDIM];

// ---------------------------------------------------------------------------
__device__ __forceinline__ uint32_t smem_u32(const void* p) {
    uint32_t a;
    asm("{ .reg .u64 t; cvta.to.shared.u64 t, %1; cvt.u32.u64 %0, t; }" : "=r"(a) : "l"(p));
    return a;
}
__device__ __forceinline__ void cp_async16(uint32_t dst, const void* src) {
    asm volatile("cp.async.cg.shared.global [%0], [%1], 16;" :: "r"(dst), "l"(src));
}
#define CP_COMMIT()  asm volatile("cp.async.commit_group;" ::: "memory")
#define CP_WAIT_1()  asm volatile("cp.async.wait_group 1;" ::: "memory")
#define CP_WAIT_0()  asm volatile("cp.async.wait_group 0;" ::: "memory")

__device__ __forceinline__ void ldsm4(uint32_t& r0, uint32_t& r1, uint32_t& r2, uint32_t& r3,
                                      uint32_t addr) {
    asm volatile("ldmatrix.sync.aligned.m8n8.x4.shared.b16 {%0,%1,%2,%3}, [%4];"
                 : "=r"(r0), "=r"(r1), "=r"(r2), "=r"(r3) : "r"(addr));
}
__device__ __forceinline__ void mma16816(float* c, const uint32_t* a, const uint32_t* b) {
    asm volatile(
        "mma.sync.aligned.m16n8k16.row.col.f32.bf16.bf16.f32 "
        "{%0,%1,%2,%3}, {%4,%5,%6,%7}, {%8,%9}, {%0,%1,%2,%3};"
        : "+f"(c[0]), "+f"(c[1]), "+f"(c[2]), "+f"(c[3])
        : "r"(a[0]), "r"(a[1]), "r"(a[2]), "r"(a[3]), "r"(b[0]), "r"(b[1]));
}

// ---------------------------------------------------------------------------
// Kernel 1: fold weights into W[o][k] (k = i*7 + j), split bf16
// ---------------------------------------------------------------------------
__global__ void build_W(const float* __restrict__ coef,
                        const float* __restrict__ scale_base,
                        const float* __restrict__ scale_sp) {
    int idx = blockIdx.x * blockDim.x + threadIdx.x;
    if (idx >= DIN * DOUT) return;
    int i = idx % DIN;
    int o = idx / DIN;
    float w[JPER];
    w[0] = scale_base[(size_t)o * DIN + i];
    float s = scale_sp[(size_t)o * DIN + i];
    const float* c = coef + ((size_t)o * DIN + i) * 6;
#pragma unroll
    for (int m = 0; m < 6; m++) w[1 + m] = s * c[m];
    __nv_bfloat16* dh = g_Whi + (size_t)o * KDIM + i * JPER;
    __nv_bfloat16* dl = g_Wlo + (size_t)o * KDIM + i * JPER;
#pragma unroll
    for (int j = 0; j < JPER; j++) {
        __nv_bfloat16 hi = __float2bfloat16_rn(w[j]);
        dh[j] = hi;
        dl[j] = __float2bfloat16_rn(w[j] - __bfloat162float(hi));
    }
}

// ---------------------------------------------------------------------------
// Kernel 2: augmented activations A[n][i*7+j], split bf16
// ---------------------------------------------------------------------------
__global__ void build_A(const float* __restrict__ x, int total) {
    int idx = blockIdx.x * blockDim.x + threadIdx.x;
    if (idx >= total) return;
    float v = x[idx];
    int n = idx / DIN;
    int i = idx % DIN;

    float out[JPER];
    out[0] = v / (1.0f + expf(-v));

    const float h = 2.0f / 3.0f;
    float g[10];
#pragma unroll
    for (int t = 0; t < 10; t++) g[t] = (float)(t - 3) * h - 1.0f;
    float B0[9];
#pragma unroll
    for (int t = 0; t < 9; t++) B0[t] = (v >= g[t] && v < g[t + 1]) ? 1.0f : 0.0f;
    float B1[8];
#pragma unroll
    for (int t = 0; t < 8; t++)
        B1[t] = (v - g[t]) / (g[t + 1] - g[t]) * B0[t]
              + (g[t + 2] - v) / (g[t + 2] - g[t + 1]) * B0[t + 1];
    float B2[7];
#pragma unroll
    for (int t = 0; t < 7; t++)
        B2[t] = (v - g[t]) / (g[t + 2] - g[t]) * B1[t]
              + (g[t + 3] - v) / (g[t + 3] - g[t + 1]) * B1[t + 1];
    float B3[6];
#pragma unroll
    for (int t = 0; t < 6; t++)
        B3[t] = (v - g[t]) / (g[t + 3] - g[t]) * B2[t]
              + (g[t + 4] - v) / (g[t + 4] - g[t + 1]) * B2[t + 1];
#pragma unroll
    for (int m = 0; m < 6; m++) out[1 + m] = B3[m];

    __nv_bfloat16* dh = g_Ahi + (size_t)n * KDIM + i * JPER;
    __nv_bfloat16* dl = g_Alo + (size_t)n * KDIM + i * JPER;
#pragma unroll
    for (int j = 0; j < JPER; j++) {
        __nv_bfloat16 hi = __float2bfloat16_rn(out[j]);
        dh[j] = hi;
        dl[j] = __float2bfloat16_rn(out[j] - __bfloat162float(hi));
    }
}

// ---------------------------------------------------------------------------
// Kernel 3: HMMA GEMM  C[8192 x 768] = A @ W^T + bias
//   split-bf16: Ahi*Bhi + Ahi*Blo + Alo*Bhi, fp32 accum
//   CTA 128x128, 8 warps (2x4), warp tile 64x32, BK=32, double buffer
// ---------------------------------------------------------------------------
#define TILE_BYTES (MT * ROWB)         // 128*80 = 10240
#define OFF_AHI 0
#define OFF_ALO (TILE_BYTES)
#define OFF_BHI (2 * TILE_BYTES)
#define OFF_BLO (3 * TILE_BYTES)
#define STAGE_BYTES (4 * TILE_BYTES)   // 40960
#define GEMM_SMEM (2 * STAGE_BYTES)    // 81920

__device__ __forceinline__ void load_stage(uint32_t sbase, int k0, int m0, int n0, int tid) {
    // 4 tiles x 128 rows x 2 16B-chunks... rows of 32 bf16 = 64B = 4 chunks of 16B
    // per tile: 512 chunks; 256 threads -> 2 chunks each
#pragma unroll
    for (int r = 0; r < 2; r++) {
        int idx = tid + r * 256;        // 0..511
        int row = idx >> 2;
        int c16 = idx & 3;
        uint32_t so = (uint32_t)(row * ROWB + c16 * 16);
        size_t gA = (size_t)(m0 + row) * KDIM + k0 + c16 * 8;
        size_t gB = (size_t)(n0 + row) * KDIM + k0 + c16 * 8;
        cp_async16(sbase + OFF_AHI + so, g_Ahi + gA);
        cp_async16(sbase + OFF_ALO + so, g_Alo + gA);
        cp_async16(sbase + OFF_BHI + so, g_Whi + gB);
        cp_async16(sbase + OFF_BLO + so, g_Wlo + gB);
    }
}

__global__ __launch_bounds__(256) void kan_gemm(const float* __restrict__ bias,
                                                float* __restrict__ C) {
    extern __shared__ char smem[];
    uint32_t sb = smem_u32(smem);
    const int tid = threadIdx.x;
    const int wid = tid >> 5;
    const int lane = tid & 31;
    const int wm = wid >> 2;            // 0..1  (64 rows each)
    const int wn = wid & 3;             // 0..3  (32 cols each)
    const int n0 = blockIdx.x * NT;
    const int m0 = blockIdx.y * MT;

    float acc[4][4][4];                 // [mt][nt][4]
#pragma unroll
    for (int i = 0; i < 4; i++)
#pragma unroll
        for (int j = 0; j < 4; j++)
#pragma unroll
            for (int q = 0; q < 4; q++) acc[i][j][q] = 0.0f;

    // ldmatrix source addresses (within a tile), per-lane:
    //  A (16x16, x4):  row = lane%16,            colByte = (lane/16)*16
    //  B (2 n-tiles):  row = lane%8 + (lane/16)*8, colByte = ((lane/8)&1)*16
    const uint32_t aRow = lane & 15;
    const uint32_t aCol = (lane >> 4) << 4;
    const uint32_t bRow = (lane & 7) + ((lane >> 4) << 3);
    const uint32_t bCol = ((lane >> 3) & 1) << 4;

    load_stage(sb, 0, m0, n0, tid);
    CP_COMMIT();

    for (int it = 0; it < NCHUNK; it++) {
        const uint32_t st = sb + (uint32_t)(it & 1) * STAGE_BYTES;
        if (it + 1 < NCHUNK) {
            load_stage(sb + (uint32_t)((it + 1) & 1) * STAGE_BYTES, (it + 1) * BK, m0, n0, tid);
            CP_COMMIT();
            CP_WAIT_1();
        } else {
            CP_WAIT_0();
        }
        __syncthreads();

#pragma unroll
        for (int k16 = 0; k16 < 2; k16++) {
            const uint32_t kByte = (uint32_t)(k16 * 32);
            uint32_t aHi[4][4], aLo[4][4], bb[4][2];

            // A hi fragments (4 m-tiles of 16)
#pragma unroll
            for (int mt = 0; mt < 4; mt++) {
                uint32_t base = st + OFF_AHI
                    + (uint32_t)(wm * 64 + mt * 16 + aRow) * ROWB + kByte + aCol;
                ldsm4(aHi[mt][0], aHi[mt][1], aHi[mt][2], aHi[mt][3], base);
            }
            // B hi fragments (4 n-tiles of 8, two per ldsm4)
#pragma unroll
            for (int np = 0; np < 2; np++) {
                uint32_t base = st + OFF_BHI
                    + (uint32_t)(wn * 32 + np * 16 + bRow) * ROWB + kByte + bCol;
                ldsm4(bb[np * 2][0], bb[np * 2][1], bb[np * 2 + 1][0], bb[np * 2 + 1][1], base);
            }
            // pass 1: Ahi * Bhi
#pragma unroll
            for (int mt = 0; mt < 4; mt++)
#pragma unroll
                for (int nt = 0; nt < 4; nt++) mma16816(acc[mt][nt], aHi[mt], bb[nt]);

            // A lo fragments, pass 3: Alo * Bhi
#pragma unroll
            for (int mt = 0; mt < 4; mt++) {
                uint32_t base = st + OFF_ALO
                    + (uint32_t)(wm * 64 + mt * 16 + aRow) * ROWB + kByte + aCol;
                ldsm4(aLo[mt][0], aLo[mt][1], aLo[mt][2], aLo[mt][3], base);
            }
#pragma unroll
            for (int mt = 0; mt < 4; mt++)
#pragma unroll
                for (int nt = 0; nt < 4; nt++) mma16816(acc[mt][nt], aLo[mt], bb[nt]);

            // B lo fragments (overwrite bb), pass 2: Ahi * Blo
#pragma unroll
            for (int np = 0; np < 2; np++) {
                uint32_t base = st + OFF_BLO
                    + (uint32_t)(wn * 32 + np * 16 + bRow) * ROWB + kByte + bCol;
                ldsm4(bb[np * 2][0], bb[np * 2][1], bb[np * 2 + 1][0], bb[np * 2 + 1][1], base);
            }
#pragma unroll
            for (int mt = 0; mt < 4; mt++)
#pragma unroll
                for (int nt = 0; nt < 4; nt++) mma16816(acc[mt][nt], aHi[mt], bb[nt]);
        }
        __syncthreads();
    }

    // epilogue: add bias, write
    const int g4 = lane >> 2;           // 0..7
    const int tg = lane & 3;            // 0..3
#pragma unroll
    for (int mt = 0; mt < 4; mt++) {
#pragma unroll
        for (int nt = 0; nt < 4; nt++) {
            int row = m0 + wm * 64 + mt * 16 + g4;
            int col = n0 + wn * 32 + nt * 8 + tg * 2;
            float b0 = bias[col], b1 = bias[col + 1];
            float2 v0 = {acc[mt][nt][0] + b0, acc[mt][nt][1] + b1};
            float2 v1 = {acc[mt][nt][2] + b0, acc[mt][nt][3] + b1};
            *(float2*)&C[(size_t)row * DOUT + col] = v0;
            *(float2*)&C[(size_t)(row + 8) * DOUT + col] = v1;
        }
    }
}

// ---------------------------------------------------------------------------
extern "C" void kernel_launch(void* const* d_in, const int* in_sizes, int n_in,
                              void* d_out, int out_size) {
    const float* x          = (const float*)d_in[0];
    const float* coef       = (const float*)d_in[1];
    const float* scale_base = (const float*)d_in[2];
    const float* scale_sp   = (const float*)d_in[3];
    const float* bias       = (const float*)d_in[4];
    float* out = (float*)d_out;

    int N = in_sizes[0] / DIN;     // 8192
    int totalX = N * DIN;

    cudaFuncSetAttribute(kan_gemm, cudaFuncAttributeMaxDynamicSharedMemorySize, GEMM_SMEM);

    build_W<<<(DIN * DOUT + 255) / 256, 256>>>(coef, scale_base, scale_sp);
    build_A<<<(totalX + 255) / 256, 256>>>(x, totalX);

    dim3 grid(DOUT / NT, N / MT);  // (6, 64) = 384 CTAs
    kan_gemm<<<grid, 256, GEMM_SMEM>>>(bias, out);
}

// round 6
// speedup vs baseline: 3.2627x; 1.6159x over previous
#include <cuda_runtime.h>
#include <cuda_fp16.h>
#include <math.h>
#include <cstdint>

#define DIN   768
#define DOUT  768
#define NMAX  8192
#define JPER  7
#define KDIM  (DIN * JPER)   // 5376

// GEMM tiling
#define MT    128
#define NT    128
#define BK    32                 // K per chunk (fp16 elems)
#define NCHUNK (KDIM / BK)       // 168
#define ROWB  80                 // 32*2 + 16 pad bytes per smem row

// Scratch: fp16 activations (single) and split-fp16 folded weights (K-major)
__device__ __align__(128) __half g_A  [(size_t)NMAX * KDIM];
__device__ __align__(128) __half g_Whi[(size_t)DOUT * KDIM];
__device__ __align__(128) __half g_Wlo[(size_t)DOUT * KDIM];

// ---------------------------------------------------------------------------
__device__ __forceinline__ uint32_t smem_u32(const void* p) {
    uint32_t a;
    asm("{ .reg .u64 t; cvta.to.shared.u64 t, %1; cvt.u32.u64 %0, t; }" : "=r"(a) : "l"(p));
    return a;
}
__device__ __forceinline__ void cp_async16(uint32_t dst, const void* src) {
    asm volatile("cp.async.cg.shared.global [%0], [%1], 16;" :: "r"(dst), "l"(src));
}
#define CP_COMMIT()  asm volatile("cp.async.commit_group;" ::: "memory")
#define CP_WAIT_1()  asm volatile("cp.async.wait_group 1;" ::: "memory")
#define CP_WAIT_0()  asm volatile("cp.async.wait_group 0;" ::: "memory")

__device__ __forceinline__ void ldsm4(uint32_t& r0, uint32_t& r1, uint32_t& r2, uint32_t& r3,
                                      uint32_t addr) {
    asm volatile("ldmatrix.sync.aligned.m8n8.x4.shared.b16 {%0,%1,%2,%3}, [%4];"
                 : "=r"(r0), "=r"(r1), "=r"(r2), "=r"(r3) : "r"(addr));
}
__device__ __forceinline__ void mma16816(float* c, const uint32_t* a, const uint32_t* b) {
    asm volatile(
        "mma.sync.aligned.m16n8k16.row.col.f32.f16.f16.f32 "
        "{%0,%1,%2,%3}, {%4,%5,%6,%7}, {%8,%9}, {%0,%1,%2,%3};"
        : "+f"(c[0]), "+f"(c[1]), "+f"(c[2]), "+f"(c[3])
        : "r"(a[0]), "r"(a[1]), "r"(a[2]), "r"(a[3]), "r"(b[0]), "r"(b[1]));
}

// ---------------------------------------------------------------------------
// Kernel 1: fold weights into W[o][k] (k = i*7 + j), split fp16
// ---------------------------------------------------------------------------
__global__ void build_W(const float* __restrict__ coef,
                        const float* __restrict__ scale_base,
                        const float* __restrict__ scale_sp) {
    int idx = blockIdx.x * blockDim.x + threadIdx.x;
    if (idx >= DIN * DOUT) return;
    int i = idx % DIN;
    int o = idx / DIN;
    float w[JPER];
    w[0] = scale_base[(size_t)o * DIN + i];
    float s = scale_sp[(size_t)o * DIN + i];
    const float* c = coef + ((size_t)o * DIN + i) * 6;
#pragma unroll
    for (int m = 0; m < 6; m++) w[1 + m] = s * c[m];
    __half* dh = g_Whi + (size_t)o * KDIM + i * JPER;
    __half* dl = g_Wlo + (size_t)o * KDIM + i * JPER;
#pragma unroll
    for (int j = 0; j < JPER; j++) {
        __half hi = __float2half_rn(w[j]);
        dh[j] = hi;
        dl[j] = __float2half_rn(w[j] - __half2float(hi));
    }
}

// ---------------------------------------------------------------------------
// Kernel 2: augmented activations A[n][i*7+j], fp16
// ---------------------------------------------------------------------------
__global__ void build_A(const float* __restrict__ x, int total) {
    int idx = blockIdx.x * blockDim.x + threadIdx.x;
    if (idx >= total) return;
    float v = x[idx];
    int n = idx / DIN;
    int i = idx % DIN;

    float out[JPER];
    out[0] = v / (1.0f + expf(-v));

    const float h = 2.0f / 3.0f;
    float g[10];
#pragma unroll
    for (int t = 0; t < 10; t++) g[t] = (float)(t - 3) * h - 1.0f;
    float B0[9];
#pragma unroll
    for (int t = 0; t < 9; t++) B0[t] = (v >= g[t] && v < g[t + 1]) ? 1.0f : 0.0f;
    float B1[8];
#pragma unroll
    for (int t = 0; t < 8; t++)
        B1[t] = (v - g[t]) / (g[t + 1] - g[t]) * B0[t]
              + (g[t + 2] - v) / (g[t + 2] - g[t + 1]) * B0[t + 1];
    float B2[7];
#pragma unroll
    for (int t = 0; t < 7; t++)
        B2[t] = (v - g[t]) / (g[t + 2] - g[t]) * B1[t]
              + (g[t + 3] - v) / (g[t + 3] - g[t + 1]) * B1[t + 1];
    float B3[6];
#pragma unroll
    for (int t = 0; t < 6; t++)
        B3[t] = (v - g[t]) / (g[t + 3] - g[t]) * B2[t]
              + (g[t + 4] - v) / (g[t + 4] - g[t + 1]) * B2[t + 1];
#pragma unroll
    for (int m = 0; m < 6; m++) out[1 + m] = B3[m];

    __half* dst = g_A + (size_t)n * KDIM + i * JPER;
#pragma unroll
    for (int j = 0; j < JPER; j++) dst[j] = __float2half_rn(out[j]);
}

// ---------------------------------------------------------------------------
// Kernel 3: HMMA GEMM  C[8192 x 768] = A @ (Whi+Wlo)^T + bias
//   fp16 2-pass, fp32 accum. CTA 128x128, 8 warps (2x4), warp 64x32, BK=32.
// ---------------------------------------------------------------------------
#define TILE_BYTES (MT * ROWB)         // 10240
#define OFF_A   0
#define OFF_BHI (TILE_BYTES)
#define OFF_BLO (2 * TILE_BYTES)
#define STAGE_BYTES (3 * TILE_BYTES)   // 30720
#define GEMM_SMEM (2 * STAGE_BYTES)    // 61440

__device__ __forceinline__ void load_stage(uint32_t sbase, int k0, int m0, int n0, int tid) {
    // 3 tiles x (128 rows x 4 16B-chunks) = 1536 chunks; 256 threads -> 6 each
#pragma unroll
    for (int r = 0; r < 2; r++) {
        int idx = tid + r * 256;        // 0..511
        int row = idx >> 2;
        int c16 = idx & 3;
        uint32_t so = (uint32_t)(row * ROWB + c16 * 16);
        size_t gA = (size_t)(m0 + row) * KDIM + k0 + c16 * 8;
        size_t gB = (size_t)(n0 + row) * KDIM + k0 + c16 * 8;
        cp_async16(sbase + OFF_A + so, g_A + gA);
        cp_async16(sbase + OFF_BHI + so, g_Whi + gB);
        cp_async16(sbase + OFF_BLO + so, g_Wlo + gB);
    }
}

__global__ __launch_bounds__(256, 2) void kan_gemm(const float* __restrict__ bias,
                                                   float* __restrict__ C) {
    extern __shared__ char smem[];
    uint32_t sb = smem_u32(smem);
    const int tid = threadIdx.x;
    const int wid = tid >> 5;
    const int lane = tid & 31;
    const int wm = wid >> 2;            // 0..1 (64 rows each)
    const int wn = wid & 3;             // 0..3 (32 cols each)
    const int n0 = blockIdx.x * NT;
    const int m0 = blockIdx.y * MT;

    float acc[4][4][4];
#pragma unroll
    for (int i = 0; i < 4; i++)
#pragma unroll
        for (int j = 0; j < 4; j++)
#pragma unroll
            for (int q = 0; q < 4; q++) acc[i][j][q] = 0.0f;

    const uint32_t aRow = lane & 15;
    const uint32_t aCol = (lane >> 4) << 4;
    const uint32_t bRow = (lane & 7) + ((lane >> 4) << 3);
    const uint32_t bCol = ((lane >> 3) & 1) << 4;

    load_stage(sb, 0, m0, n0, tid);
    CP_COMMIT();

    for (int it = 0; it < NCHUNK; it++) {
        const uint32_t st = sb + (uint32_t)(it & 1) * STAGE_BYTES;
        if (it + 1 < NCHUNK) {
            load_stage(sb + (uint32_t)((it + 1) & 1) * STAGE_BYTES, (it + 1) * BK, m0, n0, tid);
            CP_COMMIT();
            CP_WAIT_1();
        } else {
            CP_WAIT_0();
        }
        __syncthreads();

#pragma unroll
        for (int k16 = 0; k16 < 2; k16++) {
            const uint32_t kByte = (uint32_t)(k16 * 32);
            uint32_t aa[4][4], bb[4][2];

            // A fragments (4 m-tiles of 16), reused for both passes
#pragma unroll
            for (int mt = 0; mt < 4; mt++) {
                uint32_t base = st + OFF_A
                    + (uint32_t)(wm * 64 + mt * 16 + aRow) * ROWB + kByte + aCol;
                ldsm4(aa[mt][0], aa[mt][1], aa[mt][2], aa[mt][3], base);
            }
            // pass 1: A * Whi
#pragma unroll
            for (int np = 0; np < 2; np++) {
                uint32_t base = st + OFF_BHI
                    + (uint32_t)(wn * 32 + np * 16 + bRow) * ROWB + kByte + bCol;
                ldsm4(bb[np * 2][0], bb[np * 2][1], bb[np * 2 + 1][0], bb[np * 2 + 1][1], base);
            }
#pragma unroll
            for (int mt = 0; mt < 4; mt++)
#pragma unroll
                for (int nt = 0; nt < 4; nt++) mma16816(acc[mt][nt], aa[mt], bb[nt]);

            // pass 2: A * Wlo
#pragma unroll
            for (int np = 0; np < 2; np++) {
                uint32_t base = st + OFF_BLO
                    + (uint32_t)(wn * 32 + np * 16 + bRow) * ROWB + kByte + bCol;
                ldsm4(bb[np * 2][0], bb[np * 2][1], bb[np * 2 + 1][0], bb[np * 2 + 1][1], base);
            }
#pragma unroll
            for (int mt = 0; mt < 4; mt++)
#pragma unroll
                for (int nt = 0; nt < 4; nt++) mma16816(acc[mt][nt], aa[mt], bb[nt]);
        }
        __syncthreads();
    }

    // epilogue: add bias, write
    const int g4 = lane >> 2;
    const int tg = lane & 3;
#pragma unroll
    for (int mt = 0; mt < 4; mt++) {
#pragma unroll
        for (int nt = 0; nt < 4; nt++) {
            int row = m0 + wm * 64 + mt * 16 + g4;
            int col = n0 + wn * 32 + nt * 8 + tg * 2;
            float b0 = bias[col], b1 = bias[col + 1];
            float2 v0 = {acc[mt][nt][0] + b0, acc[mt][nt][1] + b1};
            float2 v1 = {acc[mt][nt][2] + b0, acc[mt][nt][3] + b1};
            *(float2*)&C[(size_t)row * DOUT + col] = v0;
            *(float2*)&C[(size_t)(row + 8) * DOUT + col] = v1;
        }
    }
}

// ---------------------------------------------------------------------------
extern "C" void kernel_launch(void* const* d_in, const int* in_sizes, int n_in,
                              void* d_out, int out_size) {
    const float* x          = (const float*)d_in[0];
    const float* coef       = (const float*)d_in[1];
    const float* scale_base = (const float*)d_in[2];
    const float* scale_sp   = (const float*)d_in[3];
    const float* bias       = (const float*)d_in[4];
    float* out = (float*)d_out;

    int N = in_sizes[0] / DIN;     // 8192
    int totalX = N * DIN;

    cudaFuncSetAttribute(kan_gemm, cudaFuncAttributeMaxDynamicSharedMemorySize, GEMM_SMEM);

    build_W<<<(DIN * DOUT + 255) / 256, 256>>>(coef, scale_base, scale_sp);
    build_A<<<(totalX + 255) / 256, 256>>>(x, totalX);

    dim3 grid(DOUT / NT, N / MT);  // (6, 64) = 384 CTAs
    kan_gemm<<<grid, 256, GEMM_SMEM>>>(bias, out);
}